// round 5
// baseline (speedup 1.0000x reference)
#include <cuda_runtime.h>
#include <cstdint>

// Problem constants
#define B_    8
#define IC_   16
#define H_    32
#define W_    32
#define OC_   32
#define KH_   3
#define KW_   3
#define TABLES_ 4608            // OC*IC*KH*KW
#define TPO_  144               // tables per output channel = IC*KH*KW

// Tiling
#define ROWS_PER_BLK 4
#define PW_   34                // padded width of smem tile rows
#define TROWS (ROWS_PER_BLK + 2)
#define CSTRIDE (TROWS * PW_)   // 204 floats per channel in the smem tile
#define TILE_FLOATS (IC_ * CSTRIDE)  // 3264

// Per-table record: {b, c, d, bitcast(off0 | off1<<16)}
__device__ float4 g_rec[TABLES_];
__device__ float  g_Asum[OC_];

// ---------------------------------------------------------------------------
// Kernel A: precompute bilinear coefficients + packed smem offsets + Asum[oc]
// ---------------------------------------------------------------------------
__global__ void precompute_kernel(const float* __restrict__ w_luts,
                                  const int* __restrict__ mc,
                                  const int* __restrict__ mkh,
                                  const int* __restrict__ mkw) {
    int t = blockIdx.x * blockDim.x + threadIdx.x;
    if (t < TABLES_) {
        float w0 = w_luts[4*t+0];
        float w1 = w_luts[4*t+1];
        float w2 = w_luts[4*t+2];
        float w3 = w_luts[4*t+3];
        float bb = 0.25f * (-w0 + w1 - w2 + w3);
        float cc = 0.25f * (-w0 - w1 + w2 + w3);
        float dd = 0.25f * ( w0 - w1 - w2 + w3);
        int m0 = 2*t, m1 = 2*t + 1;
        unsigned off0 = (unsigned)(mc[m0]*CSTRIDE + mkh[m0]*PW_ + mkw[m0]);
        unsigned off1 = (unsigned)(mc[m1]*CSTRIDE + mkh[m1]*PW_ + mkw[m1]);
        unsigned packed = off0 | (off1 << 16);
        g_rec[t] = make_float4(bb, cc, dd, __uint_as_float(packed));
    }
    // Asum[oc] = 0.25 * sum over the oc's 144 tables of (w0+w1+w2+w3)
    if (blockIdx.x == 0 && threadIdx.x < OC_) {
        int oc = threadIdx.x;
        const float4* w4 = reinterpret_cast<const float4*>(w_luts) + oc * TPO_;
        float s = 0.0f;
        #pragma unroll 4
        for (int r = 0; r < TPO_; r++) {
            float4 v = w4[r];
            s += (v.x + v.y) + (v.z + v.w);
        }
        g_Asum[oc] = 0.25f * s;
    }
}

// ---------------------------------------------------------------------------
// Kernel B: main LUT-conv.
// grid = (row_tiles=8, oc_groups=8, batch=8), block = 128 threads.
// Each block: stage padded input tile (IC x 6 x 34) to smem, then each of the
// 4 warps handles one oc: loop 144 tables, 2 conflict-free smem gathers per
// pixel, 4 pixels (rows) per thread via LDS immediate offsets.
// ---------------------------------------------------------------------------
__global__ __launch_bounds__(128)
void lut_conv_kernel(const float* __restrict__ in, float* __restrict__ out) {
    __shared__ float s_in[TILE_FLOATS];

    const int rt = blockIdx.x;        // row tile 0..7
    const int og = blockIdx.y;        // oc group 0..7
    const int b  = blockIdx.z;        // batch 0..7
    const int oh0 = rt * ROWS_PER_BLK;

    // ---- stage padded input tile for this (b, row-tile) ----
    const float* inb = in + (size_t)b * IC_ * H_ * W_;
    for (int idx = threadIdx.x; idx < TILE_FLOATS; idx += 128) {
        int c   = idx / CSTRIDE;
        int rem = idx - c * CSTRIDE;
        int lr  = rem / PW_;
        int pw  = rem - lr * PW_;
        int ih  = oh0 + lr - 1;       // padded row -> input row
        int iw  = pw - 1;             // padded col -> input col
        float v = 0.0f;
        if ((unsigned)ih < (unsigned)H_ && (unsigned)iw < (unsigned)W_)
            v = inb[(c * H_ + ih) * W_ + iw];
        s_in[idx] = v;
    }
    __syncthreads();

    const int lane = threadIdx.x & 31;
    const int warp = threadIdx.x >> 5;
    const int oc   = og * 4 + warp;

    const float4* __restrict__ rec = g_rec + oc * TPO_;
    const float asum = g_Asum[oc];

    float acc0 = asum, acc1 = asum, acc2 = asum, acc3 = asum;

    // Base pointer for this lane's pixel column; pixel p (row) adds p*PW_ as
    // an immediate offset inside the LDS instructions.
    const float* __restrict__ sp = s_in + lane;

    #pragma unroll 8
    for (int r = 0; r < TPO_; r++) {
        float4 rc = __ldg(rec + r);
        unsigned pk = __float_as_uint(rc.w);
        const float* p0 = sp + (pk & 0xFFFFu);
        const float* p1 = sp + (pk >> 16);

        float x00 = p0[0];
        float x01 = p0[PW_];
        float x02 = p0[2*PW_];
        float x03 = p0[3*PW_];
        float x10 = p1[0];
        float x11 = p1[PW_];
        float x12 = p1[2*PW_];
        float x13 = p1[3*PW_];

        acc0 = fmaf(rc.x, x00, acc0);
        acc0 = fmaf(rc.y, x10, acc0);
        acc0 = fmaf(rc.z, x00 * x10, acc0);

        acc1 = fmaf(rc.x, x01, acc1);
        acc1 = fmaf(rc.y, x11, acc1);
        acc1 = fmaf(rc.z, x01 * x11, acc1);

        acc2 = fmaf(rc.x, x02, acc2);
        acc2 = fmaf(rc.y, x12, acc2);
        acc2 = fmaf(rc.z, x02 * x12, acc2);

        acc3 = fmaf(rc.x, x03, acc3);
        acc3 = fmaf(rc.y, x13, acc3);
        acc3 = fmaf(rc.z, x03 * x13, acc3);
    }

    // ---- write out: out[b][oc][oh0+p][lane], coalesced over lanes ----
    float* ob = out + (((size_t)b * OC_ + oc) * H_ + oh0) * W_ + lane;
    ob[0]      = acc0;
    ob[W_]     = acc1;
    ob[2*W_]   = acc2;
    ob[3*W_]   = acc3;
}

// ---------------------------------------------------------------------------
// Launch
// ---------------------------------------------------------------------------
extern "C" void kernel_launch(void* const* d_in, const int* in_sizes, int n_in,
                              void* d_out, int out_size) {
    const float* input  = (const float*)d_in[0];   // (8,16,32,32)
    const float* w_luts = (const float*)d_in[1];   // (4608,4)
    const int*   mc     = (const int*)d_in[2];     // (9216,)
    const int*   mkh    = (const int*)d_in[3];     // (9216,)
    const int*   mkw    = (const int*)d_in[4];     // (9216,)
    float*       out    = (float*)d_out;           // (8,32,32,32)

    precompute_kernel<<<(TABLES_ + 255) / 256, 256>>>(w_luts, mc, mkh, mkw);

    dim3 grid(H_ / ROWS_PER_BLK, OC_ / 4, B_);     // (8, 8, 8)
    lut_conv_kernel<<<grid, 128>>>(input, out);
}

// round 6
// speedup vs baseline: 1.6152x; 1.6152x over previous
#include <cuda_runtime.h>
#include <cstdint>

// Problem constants
#define B_    8
#define IC_   16
#define H_    32
#define W_    32
#define OC_   32
#define TABLES_ 4608            // OC*IC*KH*KW
#define TPO_  144               // tables per output channel
#define HALF_ 72                // tables per warp (2-way split)

// Tiling
#define ROWS_PER_BLK 4
#define PW_   34                // padded width of smem tile rows
#define TROWS (ROWS_PER_BLK + 2)
#define CSTRIDE (TROWS * PW_)   // 204 floats per channel
#define TILE_FLOATS (IC_ * CSTRIDE)  // 3264

// ---------------------------------------------------------------------------
// Single fused kernel.
// grid = (row_tiles=8, oc_groups=8, batch=8) = 512 blocks, block = 256 (8 warps).
// Phase 1 (cooperative): stage padded input tile; compute 4*144 table records
//   {b,c,d,packed byte-offsets} + constant terms into smem.
// Phase 2: warp w -> oc = og*4 + (w&3), table half = w>>2. 72 iters, 2 smem
//   gathers per pixel, 4 pixel-rows per thread, 3 FFMA per pixel-eval.
// Phase 3: pairwise warp reduction in smem + constant-term reduction, store.
// ---------------------------------------------------------------------------
__global__ __launch_bounds__(256)
void lut_conv_fused(const float* __restrict__ in,
                    const float* __restrict__ w_luts,
                    const int* __restrict__ mc,
                    const int* __restrict__ mkh,
                    const int* __restrict__ mkw,
                    float* __restrict__ out) {
    __shared__ float  s_in[TILE_FLOATS];        // 13056 B
    __shared__ float4 s_rec[4 * TPO_];          //  9216 B  [ocg*144 + r]
    __shared__ float  s_a[4][TPO_];             //  2304 B  constant terms
    __shared__ float  s_red[4][4][32];          //  2048 B  partner accumulators

    const int tid = threadIdx.x;
    const int rt  = blockIdx.x;        // row tile 0..7
    const int og  = blockIdx.y;        // oc group 0..7
    const int b   = blockIdx.z;        // batch 0..7
    const int oh0 = rt * ROWS_PER_BLK;

    // ---- Phase 1a: stage padded input tile ----
    const float* inb = in + (size_t)b * IC_ * H_ * W_;
    for (int idx = tid; idx < TILE_FLOATS; idx += 256) {
        int c   = idx / CSTRIDE;
        int rem = idx - c * CSTRIDE;
        int lr  = rem / PW_;
        int pw  = rem - lr * PW_;
        int ih  = oh0 + lr - 1;
        int iw  = pw - 1;
        float v = 0.0f;
        if ((unsigned)ih < (unsigned)H_ && (unsigned)iw < (unsigned)W_)
            v = inb[(c * H_ + ih) * W_ + iw];
        s_in[idx] = v;
    }

    // ---- Phase 1b: compute the 4*144 records for this oc group ----
    for (int j = tid; j < 4 * TPO_; j += 256) {
        int ocg = j / TPO_;
        int r   = j - ocg * TPO_;
        int t   = (og * 4 + ocg) * TPO_ + r;
        float4 w = __ldg(reinterpret_cast<const float4*>(w_luts) + t);
        float bb = 0.25f * (-w.x + w.y - w.z + w.w);
        float cc = 0.25f * (-w.x - w.y + w.z + w.w);
        float dd = 0.25f * ( w.x - w.y - w.z + w.w);
        s_a[ocg][r] = 0.25f * ((w.x + w.y) + (w.z + w.w));
        int m0 = 2 * t, m1 = 2 * t + 1;
        // byte offsets into the smem tile (pre-scaled by 4), max 12520 < 2^16
        unsigned off0 = (unsigned)((mc[m0] * CSTRIDE + mkh[m0] * PW_ + mkw[m0]) * 4);
        unsigned off1 = (unsigned)((mc[m1] * CSTRIDE + mkh[m1] * PW_ + mkw[m1]) * 4);
        s_rec[j] = make_float4(bb, cc, dd, __uint_as_float(off0 | (off1 << 16)));
    }
    __syncthreads();

    // ---- Phase 2: main loop ----
    const int lane = tid & 31;
    const int warp = tid >> 5;
    const int ocg  = warp & 3;         // oc within group
    const int half = warp >> 2;        // table half 0/1
    const int oc   = og * 4 + ocg;

    const float4* __restrict__ recp = s_rec + ocg * TPO_ + half * HALF_;
    const char*   __restrict__ spb  = (const char*)(s_in + lane);

    float acc0 = 0.f, acc1 = 0.f, acc2 = 0.f, acc3 = 0.f;

    #pragma unroll 4
    for (int r = 0; r < HALF_; r++) {
        float4 rc = recp[r];
        unsigned pk = __float_as_uint(rc.w);
        const float* p0 = (const float*)(spb + (pk & 0xFFFFu));
        const float* p1 = (const float*)(spb + (pk >> 16));

        float x00 = p0[0];
        float x01 = p0[PW_];
        float x02 = p0[2 * PW_];
        float x03 = p0[3 * PW_];
        float x10 = p1[0];
        float x11 = p1[PW_];
        float x12 = p1[2 * PW_];
        float x13 = p1[3 * PW_];

        // acc += b*x0 + c*x1 + d*x0*x1  =  c*x1 + x0*(b + d*x1)   (3 FFMA)
        float t0 = fmaf(rc.z, x10, rc.x);
        acc0 = fmaf(rc.y, x10, acc0);
        acc0 = fmaf(x00, t0, acc0);

        float t1 = fmaf(rc.z, x11, rc.x);
        acc1 = fmaf(rc.y, x11, acc1);
        acc1 = fmaf(x01, t1, acc1);

        float t2 = fmaf(rc.z, x12, rc.x);
        acc2 = fmaf(rc.y, x12, acc2);
        acc2 = fmaf(x02, t2, acc2);

        float t3 = fmaf(rc.z, x13, rc.x);
        acc3 = fmaf(rc.y, x13, acc3);
        acc3 = fmaf(x03, t3, acc3);
    }

    // ---- Phase 3: reduce halves + constant term, store ----
    if (half == 1) {
        s_red[ocg][0][lane] = acc0;
        s_red[ocg][1][lane] = acc1;
        s_red[ocg][2][lane] = acc2;
        s_red[ocg][3][lane] = acc3;
    }
    __syncthreads();
    if (half == 0) {
        // deterministic per-oc constant-term reduction (144 values)
        float s = 0.f;
        #pragma unroll
        for (int r = lane; r < TPO_; r += 32) s += s_a[ocg][r];
        #pragma unroll
        for (int o = 16; o >= 1; o >>= 1)
            s += __shfl_xor_sync(0xFFFFFFFFu, s, o);

        acc0 += s_red[ocg][0][lane] + s;
        acc1 += s_red[ocg][1][lane] + s;
        acc2 += s_red[ocg][2][lane] + s;
        acc3 += s_red[ocg][3][lane] + s;

        float* ob = out + (((size_t)b * OC_ + oc) * H_ + oh0) * W_ + lane;
        ob[0]      = acc0;
        ob[W_]     = acc1;
        ob[2 * W_] = acc2;
        ob[3 * W_] = acc3;
    }
}

// ---------------------------------------------------------------------------
// Launch
// ---------------------------------------------------------------------------
extern "C" void kernel_launch(void* const* d_in, const int* in_sizes, int n_in,
                              void* d_out, int out_size) {
    const float* input  = (const float*)d_in[0];   // (8,16,32,32)
    const float* w_luts = (const float*)d_in[1];   // (4608,4)
    const int*   mc     = (const int*)d_in[2];     // (9216,)
    const int*   mkh    = (const int*)d_in[3];     // (9216,)
    const int*   mkw    = (const int*)d_in[4];     // (9216,)
    float*       out    = (float*)d_out;           // (8,32,32,32)

    dim3 grid(H_ / ROWS_PER_BLK, OC_ / 4, B_);     // (8, 8, 8)
    lut_conv_fused<<<grid, 256>>>(input, w_luts, mc, mkh, mkw, out);
}

// round 7
// speedup vs baseline: 2.0587x; 1.2746x over previous
#include <cuda_runtime.h>
#include <cuda_fp16.h>
#include <cstdint>

// Problem constants
#define B_    8
#define IC_   16
#define H_    32
#define W_    32
#define OC_   32
#define TPO_  144               // tables per output channel
#define HALF_ 72                // tables per warp (2-way split)

// Tiling
#define ROWS_PER_BLK 4
#define PW_   36                // padded width (cols 0..33 used; 34,35 pad)
#define CQ_   (3 * PW_)         // uint2 elems per channel (kh = 0..2)
#define TILEQ (IC_ * CQ_)       // 1728 uint2 = 13824 B

__device__ __forceinline__ float2 h2f(unsigned u) {
    __half2 h = *reinterpret_cast<__half2*>(&u);
    return __half22float2(h);
}

// ---------------------------------------------------------------------------
// Fused kernel. grid = (8 row-tiles, 8 oc-groups, 8 batch) = 512 blocks,
// 256 threads (8 warps). Tile element (c,kh,pw) packs input rows
// kh..kh+3 (of the 6 padded tile rows) as 4 halves -> one LDS.64 per gather
// delivers all 4 pixel rows of one operand.
// ---------------------------------------------------------------------------
__global__ __launch_bounds__(256)
void lut_conv_fused(const float* __restrict__ in,
                    const float* __restrict__ w_luts,
                    const int* __restrict__ mc,
                    const int* __restrict__ mkh,
                    const int* __restrict__ mkw,
                    float* __restrict__ out) {
    __shared__ uint2  s_q[TILEQ];               // 13824 B packed fp16 tile
    __shared__ float4 s_rec[4 * TPO_ + 1];      //  9232 B (+1 pad for prefetch)
    __shared__ float  s_a[4][TPO_];             //  2304 B constant terms
    __shared__ float  s_red[4][4][32];          //  2048 B partner accumulators

    const int tid = threadIdx.x;
    const int rt  = blockIdx.x;
    const int og  = blockIdx.y;
    const int b   = blockIdx.z;
    const int oh0 = rt * ROWS_PER_BLK;

    // ---- Phase 1a: stage tile. Threads 0..127: one (c, col-quad) each. ----
    if (tid < 128) {
        const int c = tid >> 3;
        const int q = tid & 7;               // float4 col group: iw = 4q..4q+3
        const float4* rowp = reinterpret_cast<const float4*>(
            in + ((size_t)b * IC_ + c) * H_ * W_) + q;
        float4 f[6];
        #pragma unroll
        for (int r = 0; r < 6; r++) {
            int ih = oh0 + r - 1;
            if ((unsigned)ih < (unsigned)H_) f[r] = rowp[ih * (W_ / 4)];
            else f[r] = make_float4(0.f, 0.f, 0.f, 0.f);
        }
        const float* ff = reinterpret_cast<const float*>(f);  // ff[r*4 + j]
        #pragma unroll
        for (int kh = 0; kh < 3; kh++) {
            #pragma unroll
            for (int j = 0; j < 4; j++) {
                __half2 lo = __floats2half2_rn(ff[kh * 4 + j],       ff[(kh + 1) * 4 + j]);
                __half2 hi = __floats2half2_rn(ff[(kh + 2) * 4 + j], ff[(kh + 3) * 4 + j]);
                uint2 v;
                v.x = *reinterpret_cast<unsigned*>(&lo);
                v.y = *reinterpret_cast<unsigned*>(&hi);
                s_q[(c * 3 + kh) * PW_ + 4 * q + 1 + j] = v;
            }
        }
    } else {
        // Threads 128..255: zero the border columns pw=0 and pw=33.
        int t2 = tid - 128;
        if (t2 < 96) {
            int c   = t2 / 6;
            int rem = t2 - c * 6;
            int kh  = rem >> 1;
            int pw  = (rem & 1) ? 33 : 0;
            s_q[(c * 3 + kh) * PW_ + pw] = make_uint2(0u, 0u);
        }
    }

    // ---- Phase 1b: table records for this oc-group (576 of them) ----
    for (int j = tid; j < 4 * TPO_; j += 256) {
        int ocg = j / TPO_;
        int r   = j - ocg * TPO_;
        int t   = (og * 4 + ocg) * TPO_ + r;
        float4 w = __ldg(reinterpret_cast<const float4*>(w_luts) + t);
        float bb = 0.25f * (-w.x + w.y - w.z + w.w);
        float cc = 0.25f * (-w.x - w.y + w.z + w.w);
        float dd = 0.25f * ( w.x - w.y - w.z + w.w);
        s_a[ocg][r] = 0.25f * ((w.x + w.y) + (w.z + w.w));
        int m0 = 2 * t, m1 = 2 * t + 1;
        // byte offsets of uint2 element (c,kh,kw); lane adds lane*8
        unsigned off0 = (unsigned)(((mc[m0] * 3 + mkh[m0]) * PW_ + mkw[m0]) * 8);
        unsigned off1 = (unsigned)(((mc[m1] * 3 + mkh[m1]) * PW_ + mkw[m1]) * 8);
        s_rec[j] = make_float4(bb, cc, dd, __uint_as_float(off0 | (off1 << 16)));
    }
    if (tid == 0) s_rec[4 * TPO_] = make_float4(0.f, 0.f, 0.f, 0.f);
    __syncthreads();

    // ---- Phase 2: main loop ----
    const int lane = tid & 31;
    const int warp = tid >> 5;
    const int ocg  = warp & 3;
    const int half = warp >> 2;
    const int oc   = og * 4 + ocg;

    const float4* __restrict__ recp = s_rec + ocg * TPO_ + half * HALF_;
    const char*   __restrict__ spb  = reinterpret_cast<const char*>(s_q) + lane * 8;

    float acc0 = 0.f, acc1 = 0.f, acc2 = 0.f, acc3 = 0.f;

    // 2-stage software pipeline: record + both gathers prefetched one ahead.
    float4 rc = recp[0];
    unsigned pk = __float_as_uint(rc.w);
    uint2 q0 = *reinterpret_cast<const uint2*>(spb + (pk & 0xFFFFu));
    uint2 q1 = *reinterpret_cast<const uint2*>(spb + (pk >> 16));

    #pragma unroll 4
    for (int r = 0; r < HALF_; r++) {
        float4 rcc = rc;
        uint2  a0  = q0;
        uint2  a1  = q1;
        int rn = (r + 1 < HALF_) ? (r + 1) : (HALF_ - 1);
        rc = recp[rn];
        pk = __float_as_uint(rc.w);
        q0 = *reinterpret_cast<const uint2*>(spb + (pk & 0xFFFFu));
        q1 = *reinterpret_cast<const uint2*>(spb + (pk >> 16));

        float2 x0a = h2f(a0.x);   // x0: rows 0,1
        float2 x0b = h2f(a0.y);   // x0: rows 2,3
        float2 x1a = h2f(a1.x);   // x1: rows 0,1
        float2 x1b = h2f(a1.y);   // x1: rows 2,3

        // acc += b*x0 + c*x1 + d*x0*x1  =  c*x1 + x0*(b + d*x1)
        float t0 = fmaf(rcc.z, x1a.x, rcc.x);
        acc0 = fmaf(rcc.y, x1a.x, acc0);
        acc0 = fmaf(x0a.x, t0, acc0);

        float t1 = fmaf(rcc.z, x1a.y, rcc.x);
        acc1 = fmaf(rcc.y, x1a.y, acc1);
        acc1 = fmaf(x0a.y, t1, acc1);

        float t2 = fmaf(rcc.z, x1b.x, rcc.x);
        acc2 = fmaf(rcc.y, x1b.x, acc2);
        acc2 = fmaf(x0b.x, t2, acc2);

        float t3 = fmaf(rcc.z, x1b.y, rcc.x);
        acc3 = fmaf(rcc.y, x1b.y, acc3);
        acc3 = fmaf(x0b.y, t3, acc3);
    }

    // ---- Phase 3: reduce halves + constant term, store ----
    if (half == 1) {
        s_red[ocg][0][lane] = acc0;
        s_red[ocg][1][lane] = acc1;
        s_red[ocg][2][lane] = acc2;
        s_red[ocg][3][lane] = acc3;
    }
    __syncthreads();
    if (half == 0) {
        float s = 0.f;
        #pragma unroll
        for (int r = lane; r < TPO_; r += 32) s += s_a[ocg][r];
        #pragma unroll
        for (int o = 16; o >= 1; o >>= 1)
            s += __shfl_xor_sync(0xFFFFFFFFu, s, o);

        acc0 += s_red[ocg][0][lane] + s;
        acc1 += s_red[ocg][1][lane] + s;
        acc2 += s_red[ocg][2][lane] + s;
        acc3 += s_red[ocg][3][lane] + s;

        float* ob = out + (((size_t)b * OC_ + oc) * H_ + oh0) * W_ + lane;
        ob[0]      = acc0;
        ob[W_]     = acc1;
        ob[2 * W_] = acc2;
        ob[3 * W_] = acc3;
    }
}

// ---------------------------------------------------------------------------
extern "C" void kernel_launch(void* const* d_in, const int* in_sizes, int n_in,
                              void* d_out, int out_size) {
    const float* input  = (const float*)d_in[0];   // (8,16,32,32)
    const float* w_luts = (const float*)d_in[1];   // (4608,4)
    const int*   mc     = (const int*)d_in[2];     // (9216,)
    const int*   mkh    = (const int*)d_in[3];     // (9216,)
    const int*   mkw    = (const int*)d_in[4];     // (9216,)
    float*       out    = (float*)d_out;           // (8,32,32,32)

    dim3 grid(H_ / ROWS_PER_BLK, OC_ / 4, B_);     // (8, 8, 8)
    lut_conv_fused<<<grid, 256>>>(input, w_luts, mc, mkh, mkw, out);
}

// round 11
// speedup vs baseline: 2.0626x; 1.0019x over previous
#include <cuda_runtime.h>
#include <cuda_fp16.h>
#include <cstdint>

// Problem constants
#define B_    8
#define IC_   16
#define H_    32
#define W_    32
#define OC_   32
#define TPO_  144               // tables per output channel
#define QTR_  36                // tables per warp (4-way split)

// Tiling
#define ROWS_PER_BLK 4
#define PW_   36                // padded width (cols 0..33 used; 34,35 pad)
#define CQ_   (3 * PW_)         // uint2 elems per channel (kh = 0..2)
#define TILEQ (IC_ * CQ_)       // 1728 uint2 = 13824 B

__device__ __forceinline__ float2 h2f(unsigned u) {
    __half2 h = *reinterpret_cast<__half2*>(&u);
    return __half22float2(h);
}

// ---------------------------------------------------------------------------
// Fused kernel. grid = (8 row-tiles, 16 oc-pairs, 8 batch) = 1024 blocks,
// 256 threads (8 warps). warp w -> oc = ogp*2 + (w&1), table quarter = w>>2.
// Tile element (c,kh,pw) packs input rows kh..kh+3 as 4 halves -> one LDS.64
// per gather delivers all 4 pixel rows of one operand.
// ---------------------------------------------------------------------------
__global__ __launch_bounds__(256, 6)
void lut_conv_fused(const float* __restrict__ in,
                    const float* __restrict__ w_luts,
                    const int* __restrict__ mc,
                    const int* __restrict__ mkh,
                    const int* __restrict__ mkw,
                    float* __restrict__ out) {
    __shared__ uint2  s_q[TILEQ];               // 13824 B packed fp16 tile
    __shared__ float4 s_rec[2 * TPO_ + 1];      //  4624 B (+1 zero pad rec)
    __shared__ float  s_a[2][TPO_];             //  1152 B constant terms
    __shared__ float  s_red[2][3][4][32];       //  3072 B partner accumulators

    const int tid = threadIdx.x;
    const int rt  = blockIdx.x;        // row tile 0..7
    const int ogp = blockIdx.y;        // oc pair 0..15
    const int b   = blockIdx.z;        // batch 0..7
    const int oh0 = rt * ROWS_PER_BLK;

    // ---- Phase 1a: stage tile. Threads 0..127: one (c, col-quad) each. ----
    if (tid < 128) {
        const int c = tid >> 3;
        const int q = tid & 7;               // float4 col group: iw = 4q..4q+3
        const float4* rowp = reinterpret_cast<const float4*>(
            in + ((size_t)b * IC_ + c) * H_ * W_) + q;
        float4 f[6];
        #pragma unroll
        for (int r = 0; r < 6; r++) {
            int ih = oh0 + r - 1;
            if ((unsigned)ih < (unsigned)H_) f[r] = rowp[ih * (W_ / 4)];
            else f[r] = make_float4(0.f, 0.f, 0.f, 0.f);
        }
        const float* ff = reinterpret_cast<const float*>(f);  // ff[r*4 + j]
        #pragma unroll
        for (int kh = 0; kh < 3; kh++) {
            #pragma unroll
            for (int j = 0; j < 4; j++) {
                __half2 lo = __floats2half2_rn(ff[kh * 4 + j],       ff[(kh + 1) * 4 + j]);
                __half2 hi = __floats2half2_rn(ff[(kh + 2) * 4 + j], ff[(kh + 3) * 4 + j]);
                uint2 v;
                v.x = *reinterpret_cast<unsigned*>(&lo);
                v.y = *reinterpret_cast<unsigned*>(&hi);
                s_q[(c * 3 + kh) * PW_ + 4 * q + 1 + j] = v;
            }
        }
    } else {
        // Threads 128..255: zero border columns pw=0 and pw=33.
        int t2 = tid - 128;
        if (t2 < 96) {
            int c   = t2 / 6;
            int rem = t2 - c * 6;
            int kh  = rem >> 1;
            int pw  = (rem & 1) ? 33 : 0;
            s_q[(c * 3 + kh) * PW_ + pw] = make_uint2(0u, 0u);
        }
    }

    // ---- Phase 1b: table records for this oc pair (288 of them) ----
    for (int j = tid; j < 2 * TPO_; j += 256) {
        int ocg = j / TPO_;
        int r   = j - ocg * TPO_;
        int t   = (ogp * 2 + ocg) * TPO_ + r;
        float4 w = __ldg(reinterpret_cast<const float4*>(w_luts) + t);
        float bb = 0.25f * (-w.x + w.y - w.z + w.w);
        float cc = 0.25f * (-w.x - w.y + w.z + w.w);
        float dd = 0.25f * ( w.x - w.y - w.z + w.w);
        s_a[ocg][r] = 0.25f * ((w.x + w.y) + (w.z + w.w));
        int m0 = 2 * t, m1 = 2 * t + 1;
        // byte offsets of uint2 element (c,kh,kw); lane adds lane*8
        unsigned off0 = (unsigned)(((mc[m0] * 3 + mkh[m0]) * PW_ + mkw[m0]) * 8);
        unsigned off1 = (unsigned)(((mc[m1] * 3 + mkh[m1]) * PW_ + mkw[m1]) * 8);
        s_rec[j] = make_float4(bb, cc, dd, __uint_as_float(off0 | (off1 << 16)));
    }
    if (tid == 0) s_rec[2 * TPO_] = make_float4(0.f, 0.f, 0.f, 0.f);
    __syncthreads();

    // ---- Phase 2: main loop (36 iters per warp) ----
    const int lane = tid & 31;
    const int warp = tid >> 5;
    const int ocg  = warp & 1;         // oc within pair
    const int qtr  = warp >> 1;        // table quarter 0..3
    const int oc   = ogp * 2 + ocg;

    const float4* __restrict__ recp = s_rec + ocg * TPO_ + qtr * QTR_;
    const char*   __restrict__ spb  = reinterpret_cast<const char*>(s_q) + lane * 8;

    float acc0 = 0.f, acc1 = 0.f, acc2 = 0.f, acc3 = 0.f;

    // 2-stage software pipeline; prefetch of recp[QTR_] hits the pad/next
    // quarter's record (always a valid smem address) and is discarded.
    float4 rc = recp[0];
    unsigned pk = __float_as_uint(rc.w);
    uint2 q0 = *reinterpret_cast<const uint2*>(spb + (pk & 0xFFFFu));
    uint2 q1 = *reinterpret_cast<const uint2*>(spb + (pk >> 16));

    #pragma unroll 4
    for (int r = 0; r < QTR_; r++) {
        float4 rcc = rc;
        uint2  a0  = q0;
        uint2  a1  = q1;
        rc = recp[r + 1];
        pk = __float_as_uint(rc.w);
        q0 = *reinterpret_cast<const uint2*>(spb + (pk & 0xFFFFu));
        q1 = *reinterpret_cast<const uint2*>(spb + (pk >> 16));

        float2 x0a = h2f(a0.x);   // x0: rows 0,1
        float2 x0b = h2f(a0.y);   // x0: rows 2,3
        float2 x1a = h2f(a1.x);   // x1: rows 0,1
        float2 x1b = h2f(a1.y);   // x1: rows 2,3

        // acc += b*x0 + c*x1 + d*x0*x1  =  c*x1 + x0*(b + d*x1)
        float t0 = fmaf(rcc.z, x1a.x, rcc.x);
        acc0 = fmaf(rcc.y, x1a.x, acc0);
        acc0 = fmaf(x0a.x, t0, acc0);

        float t1 = fmaf(rcc.z, x1a.y, rcc.x);
        acc1 = fmaf(rcc.y, x1a.y, acc1);
        acc1 = fmaf(x0a.y, t1, acc1);

        float t2 = fmaf(rcc.z, x1b.x, rcc.x);
        acc2 = fmaf(rcc.y, x1b.x, acc2);
        acc2 = fmaf(x0b.x, t2, acc2);

        float t3 = fmaf(rcc.z, x1b.y, rcc.x);
        acc3 = fmaf(rcc.y, x1b.y, acc3);
        acc3 = fmaf(x0b.y, t3, acc3);
    }

    // ---- Phase 3: 4-way reduction + constant term, store ----
    if (qtr != 0) {
        s_red[ocg][qtr - 1][0][lane] = acc0;
        s_red[ocg][qtr - 1][1][lane] = acc1;
        s_red[ocg][qtr - 1][2][lane] = acc2;
        s_red[ocg][qtr - 1][3][lane] = acc3;
    }
    __syncthreads();
    if (qtr == 0) {
        // deterministic per-oc constant-term reduction (144 values)
        float s = 0.f;
        #pragma unroll
        for (int r = lane; r < TPO_; r += 32) s += s_a[ocg][r];
        #pragma unroll
        for (int o = 16; o >= 1; o >>= 1)
            s += __shfl_xor_sync(0xFFFFFFFFu, s, o);

        #pragma unroll
        for (int p = 0; p < 3; p++) {
            acc0 += s_red[ocg][p][0][lane];
            acc1 += s_red[ocg][p][1][lane];
            acc2 += s_red[ocg][p][2][lane];
            acc3 += s_red[ocg][p][3][lane];
        }
        acc0 += s; acc1 += s; acc2 += s; acc3 += s;

        float* ob = out + (((size_t)b * OC_ + oc) * H_ + oh0) * W_ + lane;
        ob[0]      = acc0;
        ob[W_]     = acc1;
        ob[2 * W_] = acc2;
        ob[3 * W_] = acc3;
    }
}

// ---------------------------------------------------------------------------
extern "C" void kernel_launch(void* const* d_in, const int* in_sizes, int n_in,
                              void* d_out, int out_size) {
    const float* input  = (const float*)d_in[0];   // (8,16,32,32)
    const float* w_luts = (const float*)d_in[1];   // (4608,4)
    const int*   mc     = (const int*)d_in[2];     // (9216,)
    const int*   mkh    = (const int*)d_in[3];     // (9216,)
    const int*   mkw    = (const int*)d_in[4];     // (9216,)
    float*       out    = (float*)d_out;           // (8,32,32,32)

    dim3 grid(H_ / ROWS_PER_BLK, OC_ / 2, B_);     // (8, 16, 8)
    lut_conv_fused<<<grid, 256>>>(input, w_luts, mc, mkh, mkw, out);
}

// round 14
// speedup vs baseline: 2.3528x; 1.1407x over previous
#include <cuda_runtime.h>
#include <cuda_fp16.h>
#include <cstdint>

// Problem constants
#define B_    8
#define IC_   16
#define H_    32
#define W_    32
#define OC_   32
#define TPO_  144               // tables per output channel
#define QTR_  36                // tables per warp (4-way split)

// Tiling
#define ROWS_PER_BLK 4
#define PW_   36                // padded width (cols 0..33 used; 34,35 pad)
#define CQ_   (3 * PW_)         // uint2 elems per channel (kh = 0..2)
#define TILEQ (IC_ * CQ_)       // 1728 uint2 = 13824 B

// ---------------------------------------------------------------------------
// Fused kernel. grid = (8 row-tiles, 16 oc-pairs, 8 batch) = 1024 blocks,
// 256 threads (8 warps). warp w -> oc = ogp*2 + (w&1), table quarter = w>>2.
// Tile element (c,kh,pw) packs input rows kh..kh+3 as 4 halves; per-table
// bilinear math done in packed fp16 (HFMA2), per-table result accumulated
// into fp32 (no cross-table fp16 error accumulation).
// Record = uint4 {b_half2, c_half2, d_half2, packed byte offsets}.
// ---------------------------------------------------------------------------
__global__ __launch_bounds__(256, 8)
void lut_conv_fused(const float* __restrict__ in,
                    const float* __restrict__ w_luts,
                    const int* __restrict__ mc,
                    const int* __restrict__ mkh,
                    const int* __restrict__ mkw,
                    float* __restrict__ out) {
    __shared__ uint2  s_q[TILEQ];               // 13824 B packed fp16 tile
    __shared__ uint4  s_rec[2 * TPO_ + 1];      //  4624 B (+1 zero pad rec)
    __shared__ float  s_a[2][TPO_];             //  1152 B constant terms
    __shared__ float  s_red[2][3][4][32];       //  3072 B partner accumulators

    const int tid = threadIdx.x;
    const int rt  = blockIdx.x;        // row tile 0..7
    const int ogp = blockIdx.y;        // oc pair 0..15
    const int b   = blockIdx.z;        // batch 0..7
    const int oh0 = rt * ROWS_PER_BLK;

    // ---- Phase 1a: stage tile. Threads 0..127: one (c, col-quad) each. ----
    if (tid < 128) {
        const int c = tid >> 3;
        const int q = tid & 7;               // float4 col group: iw = 4q..4q+3
        const float4* rowp = reinterpret_cast<const float4*>(
            in + ((size_t)b * IC_ + c) * H_ * W_) + q;
        float4 f[6];
        #pragma unroll
        for (int r = 0; r < 6; r++) {
            int ih = oh0 + r - 1;
            if ((unsigned)ih < (unsigned)H_) f[r] = rowp[ih * (W_ / 4)];
            else f[r] = make_float4(0.f, 0.f, 0.f, 0.f);
        }
        const float* ff = reinterpret_cast<const float*>(f);  // ff[r*4 + j]
        #pragma unroll
        for (int kh = 0; kh < 3; kh++) {
            #pragma unroll
            for (int j = 0; j < 4; j++) {
                __half2 lo = __floats2half2_rn(ff[kh * 4 + j],       ff[(kh + 1) * 4 + j]);
                __half2 hi = __floats2half2_rn(ff[(kh + 2) * 4 + j], ff[(kh + 3) * 4 + j]);
                uint2 v;
                v.x = *reinterpret_cast<unsigned*>(&lo);
                v.y = *reinterpret_cast<unsigned*>(&hi);
                s_q[(c * 3 + kh) * PW_ + 4 * q + 1 + j] = v;
            }
        }
    } else {
        // Threads 128..255: zero border columns pw=0 and pw=33.
        int t2 = tid - 128;
        if (t2 < 96) {
            int c   = t2 / 6;
            int rem = t2 - c * 6;
            int kh  = rem >> 1;
            int pw  = (rem & 1) ? 33 : 0;
            s_q[(c * 3 + kh) * PW_ + pw] = make_uint2(0u, 0u);
        }
    }

    // ---- Phase 1b: table records for this oc pair (288 of them) ----
    for (int j = tid; j < 2 * TPO_; j += 256) {
        int ocg = j / TPO_;
        int r   = j - ocg * TPO_;
        int t   = (ogp * 2 + ocg) * TPO_ + r;
        float4 w = __ldg(reinterpret_cast<const float4*>(w_luts) + t);
        float bb = 0.25f * (-w.x + w.y - w.z + w.w);
        float cc = 0.25f * (-w.x - w.y + w.z + w.w);
        float dd = 0.25f * ( w.x - w.y - w.z + w.w);
        s_a[ocg][r] = 0.25f * ((w.x + w.y) + (w.z + w.w));
        int m0 = 2 * t, m1 = 2 * t + 1;
        // byte offsets of uint2 element (c,kh,kw); lane adds lane*8
        unsigned off0 = (unsigned)(((mc[m0] * 3 + mkh[m0]) * PW_ + mkw[m0]) * 8);
        unsigned off1 = (unsigned)(((mc[m1] * 3 + mkh[m1]) * PW_ + mkw[m1]) * 8);
        __half2 b2 = __float2half2_rn(bb);
        __half2 c2 = __float2half2_rn(cc);
        __half2 d2 = __float2half2_rn(dd);
        uint4 rec;
        rec.x = *reinterpret_cast<unsigned*>(&b2);
        rec.y = *reinterpret_cast<unsigned*>(&c2);
        rec.z = *reinterpret_cast<unsigned*>(&d2);
        rec.w = off0 | (off1 << 16);
        s_rec[j] = rec;
    }
    if (tid == 0) s_rec[2 * TPO_] = make_uint4(0u, 0u, 0u, 0u);
    __syncthreads();

    // ---- Phase 2: main loop (36 iters per warp) ----
    const int lane = tid & 31;
    const int warp = tid >> 5;
    const int ocg  = warp & 1;         // oc within pair
    const int qtr  = warp >> 1;        // table quarter 0..3
    const int oc   = ogp * 2 + ocg;

    const uint4* __restrict__ recp = s_rec + ocg * TPO_ + qtr * QTR_;
    const char*  __restrict__ spb  = reinterpret_cast<const char*>(s_q) + lane * 8;

    float acc0 = 0.f, acc1 = 0.f, acc2 = 0.f, acc3 = 0.f;

    // 2-stage software pipeline; prefetch of recp[QTR_] hits the pad/next
    // quarter's record (always a valid smem address) and is discarded.
    uint4 rc = recp[0];
    uint2 q0 = *reinterpret_cast<const uint2*>(spb + (rc.w & 0xFFFFu));
    uint2 q1 = *reinterpret_cast<const uint2*>(spb + (rc.w >> 16));

    #pragma unroll 4
    for (int r = 0; r < QTR_; r++) {
        uint4 rcc = rc;
        uint2 a0  = q0;
        uint2 a1  = q1;
        rc = recp[r + 1];
        q0 = *reinterpret_cast<const uint2*>(spb + (rc.w & 0xFFFFu));
        q1 = *reinterpret_cast<const uint2*>(spb + (rc.w >> 16));

        __half2 b2 = *reinterpret_cast<__half2*>(&rcc.x);
        __half2 c2 = *reinterpret_cast<__half2*>(&rcc.y);
        __half2 d2 = *reinterpret_cast<__half2*>(&rcc.z);
        __half2 x0lo = *reinterpret_cast<__half2*>(&a0.x);  // x0 rows 0,1
        __half2 x0hi = *reinterpret_cast<__half2*>(&a0.y);  // x0 rows 2,3
        __half2 x1lo = *reinterpret_cast<__half2*>(&a1.x);  // x1 rows 0,1
        __half2 x1hi = *reinterpret_cast<__half2*>(&a1.y);  // x1 rows 2,3

        // v = c*x1 + x0*(b + d*x1)   (3 fp16x2 ops per row-pair)
        __half2 tlo = __hfma2(d2, x1lo, b2);
        __half2 thi = __hfma2(d2, x1hi, b2);
        __half2 vlo = __hfma2(c2, x1lo, __hmul2(x0lo, tlo));
        __half2 vhi = __hfma2(c2, x1hi, __hmul2(x0hi, thi));

        // fp32 accumulate of the per-table results
        float2 flo = __half22float2(vlo);
        float2 fhi = __half22float2(vhi);
        acc0 += flo.x;
        acc1 += flo.y;
        acc2 += fhi.x;
        acc3 += fhi.y;
    }

    // ---- Phase 3: 4-way reduction + constant term, store ----
    if (qtr != 0) {
        s_red[ocg][qtr - 1][0][lane] = acc0;
        s_red[ocg][qtr - 1][1][lane] = acc1;
        s_red[ocg][qtr - 1][2][lane] = acc2;
        s_red[ocg][qtr - 1][3][lane] = acc3;
    }
    __syncthreads();
    if (qtr == 0) {
        // deterministic per-oc constant-term reduction (144 fp32 values)
        float s = 0.f;
        #pragma unroll
        for (int r = lane; r < TPO_; r += 32) s += s_a[ocg][r];
        #pragma unroll
        for (int o = 16; o >= 1; o >>= 1)
            s += __shfl_xor_sync(0xFFFFFFFFu, s, o);

        #pragma unroll
        for (int p = 0; p < 3; p++) {
            acc0 += s_red[ocg][p][0][lane];
            acc1 += s_red[ocg][p][1][lane];
            acc2 += s_red[ocg][p][2][lane];
            acc3 += s_red[ocg][p][3][lane];
        }
        acc0 += s; acc1 += s; acc2 += s; acc3 += s;

        float* ob = out + (((size_t)b * OC_ + oc) * H_ + oh0) * W_ + lane;
        ob[0]      = acc0;
        ob[W_]     = acc1;
        ob[2 * W_] = acc2;
        ob[3 * W_] = acc3;
    }
}

// ---------------------------------------------------------------------------
extern "C" void kernel_launch(void* const* d_in, const int* in_sizes, int n_in,
                              void* d_out, int out_size) {
    const float* input  = (const float*)d_in[0];   // (8,16,32,32)
    const float* w_luts = (const float*)d_in[1];   // (4608,4)
    const int*   mc     = (const int*)d_in[2];     // (9216,)
    const int*   mkh    = (const int*)d_in[3];     // (9216,)
    const int*   mkw    = (const int*)d_in[4];     // (9216,)
    float*       out    = (float*)d_out;           // (8,32,32,32)

    dim3 grid(H_ / ROWS_PER_BLK, OC_ / 2, B_);     // (8, 16, 8)
    lut_conv_fused<<<grid, 256>>>(input, w_luts, mc, mkh, mkw, out);
}